// round 15
// baseline (speedup 1.0000x reference)
#include <cuda_runtime.h>
#include <cuda_fp16.h>
#include <math.h>
#include <stdint.h>

#define SEQ 2048
#define HID 4096
#define NQH 32
#define NKV 8
#define HD  128

// ---------------- scratch (no cudaMalloc allowed) ----------------
__device__ __half g_xh[SEQ * HID];
__device__ __half g_qh[SEQ * NQH * HD];
__device__ __half g_kh[SEQ * NKV * HD];
__device__ __half g_vh[SEQ * NKV * HD];
__device__ __half g_oh[SEQ * NQH * HD];
__device__ __half g_Wqh[HID * (NQH * HD)];   // row-major [K, N] fp16
__device__ __half g_Wkh[HID * (NKV * HD)];
__device__ __half g_Wvh[HID * (NKV * HD)];
__device__ __half g_Woh[(NQH * HD) * HID];

// ---------------- asm helpers ----------------
__device__ __forceinline__ uint32_t smem_u32(const void* p) {
    uint32_t a;
    asm("{ .reg .u64 t; cvta.to.shared.u64 t, %1; cvt.u32.u64 %0, t; }" : "=r"(a) : "l"(p));
    return a;
}
#define CP_A16(dst, src) asm volatile("cp.async.cg.shared.global [%0], [%1], 16;" :: "r"(dst), "l"(src))
#define CP_COMMIT() asm volatile("cp.async.commit_group;")
#define CP_WAIT(n)  asm volatile("cp.async.wait_group %0;" :: "n"(n))

__device__ __forceinline__ void ldsm_x4(uint32_t* r, uint32_t a) {
    asm volatile("ldmatrix.sync.aligned.m8n8.x4.shared.b16 {%0,%1,%2,%3}, [%4];"
                 : "=r"(r[0]), "=r"(r[1]), "=r"(r[2]), "=r"(r[3]) : "r"(a));
}
__device__ __forceinline__ void ldsm_x4_t(uint32_t* r, uint32_t a) {
    asm volatile("ldmatrix.sync.aligned.m8n8.x4.trans.shared.b16 {%0,%1,%2,%3}, [%4];"
                 : "=r"(r[0]), "=r"(r[1]), "=r"(r[2]), "=r"(r[3]) : "r"(a));
}
__device__ __forceinline__ void mma16816(float (&d)[4], const uint32_t (&a)[4], uint32_t b0, uint32_t b1) {
    asm volatile(
        "mma.sync.aligned.m16n8k16.row.col.f32.f16.f16.f32 "
        "{%0,%1,%2,%3}, {%4,%5,%6,%7}, {%8,%9}, {%0,%1,%2,%3};"
        : "+f"(d[0]), "+f"(d[1]), "+f"(d[2]), "+f"(d[3])
        : "r"(a[0]), "r"(a[1]), "r"(a[2]), "r"(a[3]), "r"(b0), "r"(b1));
}
__device__ __forceinline__ uint32_t pack_h2(float lo, float hi) {
    __half2 h = __floats2half2_rn(lo, hi);
    return *(uint32_t*)&h;
}

// ---------------- pre-pass: ALL fp32 -> fp16 conversions in ONE launch ----------------
#define N_X  (SEQ * HID)
#define N_WQ (HID * NQH * HD)
#define N_WK (HID * NKV * HD)
#define N_WV (HID * NKV * HD)
#define N_WO (NQH * HD * HID)

__global__ __launch_bounds__(256)
void cvt_all(const float* __restrict__ x,  const float* __restrict__ wq,
             const float* __restrict__ wk, const float* __restrict__ wv,
             const float* __restrict__ wo,
             __half* __restrict__ xh,  __half* __restrict__ wqh,
             __half* __restrict__ wkh, __half* __restrict__ wvh,
             __half* __restrict__ woh) {
    int b = blockIdx.x;
    const float* in;
    __half* out;
    if (b < N_X / 4096)                          { in = x;  out = xh;  }
    else if ((b -= N_X / 4096)  < N_WQ / 4096)   { in = wq; out = wqh; }
    else if ((b -= N_WQ / 4096) < N_WK / 4096)   { in = wk; out = wkh; }
    else if ((b -= N_WK / 4096) < N_WV / 4096)   { in = wv; out = wvh; }
    else    { b -= N_WV / 4096;                    in = wo; out = woh; }

    const int base = b * 4096 + threadIdx.x * 4;
    float4 v0 = *(const float4*)(in + base);
    float4 v1 = *(const float4*)(in + base + 1024);
    float4 v2 = *(const float4*)(in + base + 2048);
    float4 v3 = *(const float4*)(in + base + 3072);
    *(uint2*)(out + base)        = make_uint2(pack_h2(v0.x, v0.y), pack_h2(v0.z, v0.w));
    *(uint2*)(out + base + 1024) = make_uint2(pack_h2(v1.x, v1.y), pack_h2(v1.z, v1.w));
    *(uint2*)(out + base + 2048) = make_uint2(pack_h2(v2.x, v2.y), pack_h2(v2.z, v2.w));
    *(uint2*)(out + base + 3072) = make_uint2(pack_h2(v3.x, v3.y), pack_h2(v3.z, v3.w));
}
#define CVT_GRID ((N_X + N_WQ + N_WK + N_WV + N_WO) / 4096)

// ---------------- fp16 GEMM: 256 threads / 8 warps, warp tile 64x64 (round-13 config) ----------------
#define HA_STR 40
#define HB_STR 264
#define HA_ST  (128 * HA_STR * 2)
#define HB_ST  (32 * HB_STR * 2)
#define HG_SMEM (4 * (HA_ST + HB_ST))

template <typename OT>
__device__ __forceinline__
void hgemm_rm(const __half* __restrict__ A, const __half* __restrict__ W,
              OT* __restrict__ C, int Ncols, int K, int bm, int bn) {
    extern __shared__ __align__(16) __half hsm[];
    const uint32_t asb = smem_u32(hsm);
    const uint32_t bsb = asb + 4 * HA_ST;

    const int tid  = threadIdx.x;
    const int warp = tid >> 5;
    const int lane = tid & 31;
    const int g    = lane >> 2;
    const int t4   = lane & 3;
    const int wm   = warp >> 2;
    const int wn   = warp & 3;

    const __half* Asrc[2];
    uint32_t Adst[2];
    #pragma unroll
    for (int j = 0; j < 2; j++) {
        int ch = tid + j * 256;
        int row = ch >> 2, kc = (ch & 3) * 8;
        Asrc[j] = A + (size_t)(bm + row) * K + kc;
        Adst[j] = asb + (row * HA_STR + kc) * 2;
    }
    const __half* Bsrc[4];
    uint32_t Bdst[4];
    #pragma unroll
    for (int j = 0; j < 4; j++) {
        int ch = tid + j * 256;
        int row = ch >> 5, c8 = ch & 31;
        Bsrc[j] = W + (size_t)row * Ncols + bn + c8 * 8;
        Bdst[j] = bsb + (row * HB_STR + c8 * 8) * 2;
    }

    const uint32_t aBase = asb + ((wm * 64 + (lane & 7) + ((lane >> 3) & 1) * 8) * HA_STR
                                  + (lane >> 4) * 8) * 2;
    const uint32_t bBase = bsb + (((lane & 7) + ((lane >> 3) & 1) * 8) * HB_STR
                                  + wn * 64 + (lane >> 4) * 8) * 2;

    float acc[4][8][4];
    #pragma unroll
    for (int mi = 0; mi < 4; mi++)
        #pragma unroll
        for (int ni = 0; ni < 8; ni++)
            #pragma unroll
            for (int r = 0; r < 4; r++) acc[mi][ni][r] = 0.0f;

    const int iters = K >> 5;
    const size_t bAdv = (size_t)32 * Ncols;

    #pragma unroll
    for (int j = 0; j < 2; j++) CP_A16(Adst[j], Asrc[j]);
    #pragma unroll
    for (int j = 0; j < 4; j++) CP_A16(Bdst[j], Bsrc[j]);
    CP_COMMIT();
    {
        #pragma unroll
        for (int j = 0; j < 2; j++) CP_A16(Adst[j] + HA_ST, Asrc[j] + 32);
        #pragma unroll
        for (int j = 0; j < 4; j++) CP_A16(Bdst[j] + HB_ST, Bsrc[j] + bAdv);
        CP_COMMIT();
    }

    for (int i = 0; i < iters; i++) {
        if (i + 2 < iters) {
            const uint32_t ao = ((i + 2) & 3) * HA_ST;
            const uint32_t bo = ((i + 2) & 3) * HB_ST;
            const int ko = (i + 2) << 5;
            #pragma unroll
            for (int j = 0; j < 2; j++) CP_A16(Adst[j] + ao, Asrc[j] + ko);
            #pragma unroll
            for (int j = 0; j < 4; j++) CP_A16(Bdst[j] + bo, Bsrc[j] + (size_t)(i + 2) * bAdv);
            CP_COMMIT();
            CP_WAIT(2);
        } else if (i + 1 < iters) {
            CP_WAIT(1);
        } else {
            CP_WAIT(0);
        }
        __syncthreads();

        const uint32_t ao = (i & 3) * HA_ST;
        const uint32_t bo = (i & 3) * HB_ST;
        #pragma unroll
        for (int kb = 0; kb < 2; kb++) {
            uint32_t af[4][4];
            #pragma unroll
            for (int mi = 0; mi < 4; mi++)
                ldsm_x4(af[mi], aBase + ao + mi * (16 * HA_STR * 2) + kb * 32);
            uint32_t bf[4][4];
            #pragma unroll
            for (int nj = 0; nj < 4; nj++)
                ldsm_x4_t(bf[nj], bBase + bo + kb * (16 * HB_STR * 2) + nj * 32);
            #pragma unroll
            for (int mi = 0; mi < 4; mi++)
                #pragma unroll
                for (int nj = 0; nj < 4; nj++) {
                    mma16816(acc[mi][2 * nj],     af[mi], bf[nj][0], bf[nj][1]);
                    mma16816(acc[mi][2 * nj + 1], af[mi], bf[nj][2], bf[nj][3]);
                }
        }
    }

    #pragma unroll
    for (int mi = 0; mi < 4; mi++) {
        #pragma unroll
        for (int ni = 0; ni < 8; ni++) {
            int r1 = bm + wm * 64 + mi * 16 + g;
            int c  = bn + wn * 64 + ni * 8 + t4 * 2;
            if (sizeof(OT) == 2) {
                __half* Ch = (__half*)C;
                *(uint32_t*)(Ch + (size_t)r1 * Ncols + c)       = pack_h2(acc[mi][ni][0], acc[mi][ni][1]);
                *(uint32_t*)(Ch + (size_t)(r1 + 8) * Ncols + c) = pack_h2(acc[mi][ni][2], acc[mi][ni][3]);
            } else {
                float* Cf = (float*)C;
                *(float2*)(Cf + (size_t)r1 * Ncols + c)       = make_float2(acc[mi][ni][0], acc[mi][ni][1]);
                *(float2*)(Cf + (size_t)(r1 + 8) * Ncols + c) = make_float2(acc[mi][ni][2], acc[mi][ni][3]);
            }
        }
    }
}

__global__ __launch_bounds__(256, 1)
void hgemm_qkv(const __half* __restrict__ A,
               const __half* __restrict__ Wq, const __half* __restrict__ Wk,
               const __half* __restrict__ Wv,
               __half* __restrict__ Cq, __half* __restrict__ Ck, __half* __restrict__ Cv) {
    const int bx = blockIdx.x;
    const int bm = blockIdx.y * 128;
    if (bx < 16)      hgemm_rm<__half>(A, Wq, Cq, NQH * HD, HID, bm, bx * 256);
    else if (bx < 20) hgemm_rm<__half>(A, Wk, Ck, NKV * HD, HID, bm, (bx - 16) * 256);
    else              hgemm_rm<__half>(A, Wv, Cv, NKV * HD, HID, bm, (bx - 20) * 256);
}

__global__ __launch_bounds__(256, 1)
void hgemm_o(const __half* __restrict__ A, const __half* __restrict__ W,
             float* __restrict__ C) {
    hgemm_rm<float>(A, W, C, HID, NQH * HD, blockIdx.y * 128, blockIdx.x * 256);
}

// ---------------- RMSNorm + RoPE (q and k in ONE launch), in-place fp16 ----------------
#define QROWS (SEQ * NQH)
#define KROWS (SEQ * NKV)

__global__ __launch_bounds__(256)
void rmsnorm_rope_qk(__half* __restrict__ qbuf, __half* __restrict__ kbuf,
                     const float* __restrict__ qw, const float* __restrict__ kw,
                     const float* __restrict__ cosT, const float* __restrict__ sinT,
                     const int* __restrict__ pos_ids, float qscale) {
    const int lane = threadIdx.x & 31;
    int row = blockIdx.x * 8 + (threadIdx.x >> 5);

    __half* buf;
    const float* w;
    float oscale;
    int s;
    if (row < QROWS) {
        buf = qbuf; w = qw; oscale = qscale; s = row / NQH;
    } else {
        row -= QROWS;
        buf = kbuf; w = kw; oscale = 1.0f; s = row / NKV;
    }
    const int c0 = lane * 4;

    __half* rp = buf + (size_t)row * HD;
    uint2 raw = *(const uint2*)(rp + c0);
    __half2 h01 = *(__half2*)&raw.x;
    __half2 h23 = *(__half2*)&raw.y;
    float4 v = make_float4(__low2float(h01), __high2float(h01),
                           __low2float(h23), __high2float(h23));
    float4 wv = *(const float4*)(w + c0);

    float ss = v.x * v.x + v.y * v.y + v.z * v.z + v.w * v.w;
    #pragma unroll
    for (int off = 16; off > 0; off >>= 1)
        ss += __shfl_xor_sync(0xffffffffu, ss, off);
    const float inv = rsqrtf(ss * (1.0f / HD) + 1e-6f);

    float4 xn;
    xn.x = v.x * inv * wv.x; xn.y = v.y * inv * wv.y;
    xn.z = v.z * inv * wv.z; xn.w = v.w * inv * wv.w;

    float px = __shfl_xor_sync(0xffffffffu, xn.x, 16);
    float py = __shfl_xor_sync(0xffffffffu, xn.y, 16);
    float pz = __shfl_xor_sync(0xffffffffu, xn.z, 16);
    float pw = __shfl_xor_sync(0xffffffffu, xn.w, 16);
    const float sgn = (lane < 16) ? -1.0f : 1.0f;

    const int p = pos_ids[s];
    float4 c  = *(const float4*)(cosT + (size_t)p * HD + c0);
    float4 sn = *(const float4*)(sinT + (size_t)p * HD + c0);

    float ox = (xn.x * c.x + sgn * px * sn.x) * oscale;
    float oy = (xn.y * c.y + sgn * py * sn.y) * oscale;
    float oz = (xn.z * c.z + sgn * pz * sn.z) * oscale;
    float ow = (xn.w * c.w + sgn * pw * sn.w) * oscale;

    *(uint2*)(rp + c0) = make_uint2(pack_h2(ox, oy), pack_h2(oz, ow));
}

// ---------------- fp16 flash attention: 2 CTAs/SM, 2-stage ring, no Q hoist ----------------
// CTA = 32 q-rows x 4 heads (one kv head), M=128. grid (SEQ/32, NKV).
#define FSTR 136
#define FQ_HALVES (128 * FSTR)
#define FK_HALVES (64 * FSTR)
#define ATTN_SMEM ((FQ_HALVES + 4 * FK_HALVES) * 2)   // Q + 2 stages x (K+V) = 104448 B

__global__ __launch_bounds__(256, 2)
void flash_h(const __half* __restrict__ Qh, const __half* __restrict__ Kh,
             const __half* __restrict__ Vh, __half* __restrict__ Oh) {
    extern __shared__ __align__(16) __half fsm[];
    __half* Qs = fsm;
    __half* Ks = fsm + FQ_HALVES;              // 2 stages
    __half* Vs = Ks + 2 * FK_HALVES;           // 2 stages

    const int tid  = threadIdx.x;
    const int warp = tid >> 5;
    const int lane = tid & 31;
    const int g    = lane >> 2;
    const int t4   = lane & 3;
    const int wrow = warp * 16;

    const int qb    = gridDim.x - 1 - blockIdx.x;   // heavy blocks first
    const int kvh   = blockIdx.y;
    const int h0    = kvh * 4;
    const int qbase = qb * 32;

    const uint32_t qsb = smem_u32(Qs);
    const uint32_t ksb = smem_u32(Ks);
    const uint32_t vsb = smem_u32(Vs);
    const uint32_t KSTB = FK_HALVES * 2;

    const int nkb = (qbase >> 6) + 1;

    // prologue: Q + KV0
    {
        #pragma unroll
        for (int j = 0; j < 8; j++) {
            int c = tid + j * 256;
            int row = c >> 4, c8 = c & 15;
            CP_A16(qsb + (row * FSTR + c8 * 8) * 2,
                   Qh + (size_t)(qbase + (row & 31)) * (NQH * HD)
                      + (h0 + (row >> 5)) * HD + c8 * 8);
        }
        #pragma unroll
        for (int j = 0; j < 4; j++) {
            int c = tid + j * 256;
            int row = c >> 4, c8 = c & 15;
            size_t gi = (size_t)row * (NKV * HD) + kvh * HD + c8 * 8;
            CP_A16(ksb + (row * FSTR + c8 * 8) * 2, Kh + gi);
            CP_A16(vsb + (row * FSTR + c8 * 8) * 2, Vh + gi);
        }
        CP_COMMIT();
    }

    float o[16][4];
    #pragma unroll
    for (int ni = 0; ni < 16; ni++)
        #pragma unroll
        for (int r = 0; r < 4; r++) o[ni][r] = 0.0f;
    float m1 = -INFINITY, m2 = -INFINITY, l1 = 0.0f, l2 = 0.0f;

    const uint32_t qBase = qsb + ((wrow + (lane & 7) + ((lane >> 3) & 1) * 8) * FSTR
                                   + (lane >> 4) * 8) * 2;
    const uint32_t kBase = ksb + (((lane & 7) + (lane >> 4) * 8) * FSTR
                                   + ((lane >> 3) & 1) * 8) * 2;
    const uint32_t vBase = vsb + (((lane & 7) + ((lane >> 3) & 1) * 8) * FSTR
                                   + (lane >> 4) * 8) * 2;

    const int seqrel = wrow & 31;

    for (int kb = 0; kb < nkb; kb++) {
        if (kb + 1 < nkb) {
            const int st = (kb + 1) & 1;
            const int kbase1 = (kb + 1) * 64;
            #pragma unroll
            for (int j = 0; j < 4; j++) {
                int c = tid + j * 256;
                int row = c >> 4, c8 = c & 15;
                size_t gi = (size_t)(kbase1 + row) * (NKV * HD) + kvh * HD + c8 * 8;
                CP_A16(ksb + st * KSTB + (row * FSTR + c8 * 8) * 2, Kh + gi);
                CP_A16(vsb + st * KSTB + (row * FSTR + c8 * 8) * 2, Vh + gi);
            }
            CP_COMMIT();
            CP_WAIT(1);
        } else {
            CP_WAIT(0);
        }
        __syncthreads();

        const uint32_t so = (kb & 1) * KSTB;
        const int kbase = kb * 64;

        float s[8][4];
        #pragma unroll
        for (int ni = 0; ni < 8; ni++)
            #pragma unroll
            for (int r = 0; r < 4; r++) s[ni][r] = 0.0f;

        #pragma unroll
        for (int k0 = 0; k0 < HD; k0 += 16) {
            uint32_t aq[4];
            ldsm_x4(aq, qBase + k0 * 2);
            #pragma unroll
            for (int nj = 0; nj < 4; nj++) {
                uint32_t bk[4];
                ldsm_x4(bk, kBase + so + nj * (16 * FSTR * 2) + k0 * 2);
                mma16816(s[2 * nj],     aq, bk[0], bk[1]);
                mma16816(s[2 * nj + 1], aq, bk[2], bk[3]);
            }
        }

        if (kbase + 63 > qbase + seqrel) {
            const int r1 = qbase + seqrel + g;
            const int r2 = r1 + 8;
            #pragma unroll
            for (int ni = 0; ni < 8; ni++) {
                int c0 = kbase + ni * 8 + t4 * 2;
                if (c0     > r1) s[ni][0] = -1e30f;
                if (c0 + 1 > r1) s[ni][1] = -1e30f;
                if (c0     > r2) s[ni][2] = -1e30f;
                if (c0 + 1 > r2) s[ni][3] = -1e30f;
            }
        }

        float mx1 = -INFINITY, mx2 = -INFINITY;
        #pragma unroll
        for (int ni = 0; ni < 8; ni++) {
            mx1 = fmaxf(mx1, fmaxf(s[ni][0], s[ni][1]));
            mx2 = fmaxf(mx2, fmaxf(s[ni][2], s[ni][3]));
        }
        mx1 = fmaxf(mx1, __shfl_xor_sync(0xffffffffu, mx1, 1));
        mx1 = fmaxf(mx1, __shfl_xor_sync(0xffffffffu, mx1, 2));
        mx2 = fmaxf(mx2, __shfl_xor_sync(0xffffffffu, mx2, 1));
        mx2 = fmaxf(mx2, __shfl_xor_sync(0xffffffffu, mx2, 2));

        float mn1 = fmaxf(m1, mx1), mn2 = fmaxf(m2, mx2);
        float sc1 = exp2f(m1 - mn1), sc2 = exp2f(m2 - mn2);
        m1 = mn1; m2 = mn2;

        float ps1 = 0.0f, ps2 = 0.0f;
        #pragma unroll
        for (int ni = 0; ni < 8; ni++) {
            s[ni][0] = exp2f(s[ni][0] - mn1);
            s[ni][1] = exp2f(s[ni][1] - mn1);
            s[ni][2] = exp2f(s[ni][2] - mn2);
            s[ni][3] = exp2f(s[ni][3] - mn2);
            ps1 += s[ni][0] + s[ni][1];
            ps2 += s[ni][2] + s[ni][3];
        }
        ps1 += __shfl_xor_sync(0xffffffffu, ps1, 1);
        ps1 += __shfl_xor_sync(0xffffffffu, ps1, 2);
        ps2 += __shfl_xor_sync(0xffffffffu, ps2, 1);
        ps2 += __shfl_xor_sync(0xffffffffu, ps2, 2);
        l1 = l1 * sc1 + ps1;
        l2 = l2 * sc2 + ps2;

        #pragma unroll
        for (int ni = 0; ni < 16; ni++) {
            o[ni][0] *= sc1; o[ni][1] *= sc1;
            o[ni][2] *= sc2; o[ni][3] *= sc2;
        }

        #pragma unroll
        for (int j = 0; j < 4; j++) {
            uint32_t ap[4];
            ap[0] = pack_h2(s[2 * j][0],     s[2 * j][1]);
            ap[1] = pack_h2(s[2 * j][2],     s[2 * j][3]);
            ap[2] = pack_h2(s[2 * j + 1][0], s[2 * j + 1][1]);
            ap[3] = pack_h2(s[2 * j + 1][2], s[2 * j + 1][3]);
            #pragma unroll
            for (int nj = 0; nj < 8; nj++) {
                uint32_t bv[4];
                ldsm_x4_t(bv, vBase + so + j * (16 * FSTR * 2) + nj * 32);
                mma16816(o[2 * nj],     ap, bv[0], bv[1]);
                mma16816(o[2 * nj + 1], ap, bv[2], bv[3]);
            }
        }
        __syncthreads();
    }

    const float inv1 = 1.0f / l1;
    const float inv2 = 1.0f / l2;
    const int hOut = h0 + (warp >> 1);
    const int r1 = qbase + seqrel + g;
    #pragma unroll
    for (int ni = 0; ni < 16; ni++) {
        int c = ni * 8 + t4 * 2;
        *(uint32_t*)(Oh + (size_t)r1 * (NQH * HD) + hOut * HD + c) =
            pack_h2(o[ni][0] * inv1, o[ni][1] * inv1);
        *(uint32_t*)(Oh + (size_t)(r1 + 8) * (NQH * HD) + hOut * HD + c) =
            pack_h2(o[ni][2] * inv2, o[ni][3] * inv2);
    }
}

// ---------------- launch ----------------
extern "C" void kernel_launch(void* const* d_in, const int* in_sizes, int n_in,
                              void* d_out, int out_size) {
    const float* x    = (const float*)d_in[0];
    const int*   pos  = (const int*)  d_in[1];
    const float* cosT = (const float*)d_in[2];
    const float* sinT = (const float*)d_in[3];
    // d_in[4] = attn_mask — replicated exactly by causal skip
    const float* Wq   = (const float*)d_in[5];
    const float* Wk   = (const float*)d_in[6];
    const float* Wv   = (const float*)d_in[7];
    const float* Wo   = (const float*)d_in[8];
    const float* qw   = (const float*)d_in[9];
    const float* kw   = (const float*)d_in[10];
    float* out = (float*)d_out;

    __half *xh, *qh, *kh, *vh, *oh, *wqh, *wkh, *wvh, *woh;
    cudaGetSymbolAddress((void**)&xh, g_xh);
    cudaGetSymbolAddress((void**)&qh, g_qh);
    cudaGetSymbolAddress((void**)&kh, g_kh);
    cudaGetSymbolAddress((void**)&vh, g_vh);
    cudaGetSymbolAddress((void**)&oh, g_oh);
    cudaGetSymbolAddress((void**)&wqh, g_Wqh);
    cudaGetSymbolAddress((void**)&wkh, g_Wkh);
    cudaGetSymbolAddress((void**)&wvh, g_Wvh);
    cudaGetSymbolAddress((void**)&woh, g_Woh);

    cudaFuncSetAttribute(flash_h,   cudaFuncAttributeMaxDynamicSharedMemorySize, ATTN_SMEM);
    cudaFuncSetAttribute(hgemm_qkv, cudaFuncAttributeMaxDynamicSharedMemorySize, HG_SMEM);
    cudaFuncSetAttribute(hgemm_o,   cudaFuncAttributeMaxDynamicSharedMemorySize, HG_SMEM);

    // pre-pass: single fused fp32 -> fp16 conversion launch
    cvt_all<<<CVT_GRID, 256>>>(x, Wq, Wk, Wv, Wo, xh, wqh, wkh, wvh, woh);

    // fused QKV projection (256 threads, 64x64 warp tiles — round-13 config)
    hgemm_qkv<<<dim3(24, SEQ / 128), 256, HG_SMEM>>>(xh, wqh, wkh, wvh, qh, kh, vh);

    // RMSNorm + RoPE in-place on fp16 (q pre-scaled for exp2 softmax)
    rmsnorm_rope_qk<<<(QROWS + KROWS) / 8, 256>>>(qh, kh, qw, kw, cosT, sinT, pos,
                                                  0.08838834764831845f * 1.4426950408889634f);

    // causal flash attention (GQA-shared K/V, 2 CTAs/SM, heavy CTAs first)
    flash_h<<<dim3(SEQ / 32, NKV), 256, ATTN_SMEM>>>(qh, kh, vh, oh);

    // output projection
    hgemm_o<<<dim3(HID / 256, SEQ / 128), 256, HG_SMEM>>>(oh, woh, out);
}

// round 16
// speedup vs baseline: 1.0877x; 1.0877x over previous
#include <cuda_runtime.h>
#include <cuda_fp16.h>
#include <math.h>
#include <stdint.h>

#define SEQ 2048
#define HID 4096
#define NQH 32
#define NKV 8
#define HD  128

// ---------------- scratch (no cudaMalloc allowed) ----------------
__device__ __half g_xh[SEQ * HID];
__device__ __half g_qh[SEQ * NQH * HD];
__device__ __half g_kh[SEQ * NKV * HD];
__device__ __half g_vh[SEQ * NKV * HD];
__device__ __half g_oh[SEQ * NQH * HD];
__device__ __half g_Wqh[HID * (NQH * HD)];   // row-major [K, N] fp16
__device__ __half g_Wkh[HID * (NKV * HD)];
__device__ __half g_Wvh[HID * (NKV * HD)];
__device__ __half g_Woh[(NQH * HD) * HID];

// ---------------- asm helpers ----------------
__device__ __forceinline__ uint32_t smem_u32(const void* p) {
    uint32_t a;
    asm("{ .reg .u64 t; cvta.to.shared.u64 t, %1; cvt.u32.u64 %0, t; }" : "=r"(a) : "l"(p));
    return a;
}
#define CP_A16(dst, src) asm volatile("cp.async.cg.shared.global [%0], [%1], 16;" :: "r"(dst), "l"(src))
#define CP_COMMIT() asm volatile("cp.async.commit_group;")
#define CP_WAIT(n)  asm volatile("cp.async.wait_group %0;" :: "n"(n))

__device__ __forceinline__ void ldsm_x4(uint32_t* r, uint32_t a) {
    asm volatile("ldmatrix.sync.aligned.m8n8.x4.shared.b16 {%0,%1,%2,%3}, [%4];"
                 : "=r"(r[0]), "=r"(r[1]), "=r"(r[2]), "=r"(r[3]) : "r"(a));
}
__device__ __forceinline__ void ldsm_x4_t(uint32_t* r, uint32_t a) {
    asm volatile("ldmatrix.sync.aligned.m8n8.x4.trans.shared.b16 {%0,%1,%2,%3}, [%4];"
                 : "=r"(r[0]), "=r"(r[1]), "=r"(r[2]), "=r"(r[3]) : "r"(a));
}
__device__ __forceinline__ void mma16816(float (&d)[4], const uint32_t (&a)[4], uint32_t b0, uint32_t b1) {
    asm volatile(
        "mma.sync.aligned.m16n8k16.row.col.f32.f16.f16.f32 "
        "{%0,%1,%2,%3}, {%4,%5,%6,%7}, {%8,%9}, {%0,%1,%2,%3};"
        : "+f"(d[0]), "+f"(d[1]), "+f"(d[2]), "+f"(d[3])
        : "r"(a[0]), "r"(a[1]), "r"(a[2]), "r"(a[3]), "r"(b0), "r"(b1));
}
__device__ __forceinline__ uint32_t pack_h2(float lo, float hi) {
    __half2 h = __floats2half2_rn(lo, hi);
    return *(uint32_t*)&h;
}

// ---------------- pre-pass: ALL fp32 -> fp16 conversions in ONE launch ----------------
#define N_X  (SEQ * HID)
#define N_WQ (HID * NQH * HD)
#define N_WK (HID * NKV * HD)
#define N_WV (HID * NKV * HD)
#define N_WO (NQH * HD * HID)

__global__ __launch_bounds__(256)
void cvt_all(const float* __restrict__ x,  const float* __restrict__ wq,
             const float* __restrict__ wk, const float* __restrict__ wv,
             const float* __restrict__ wo,
             __half* __restrict__ xh,  __half* __restrict__ wqh,
             __half* __restrict__ wkh, __half* __restrict__ wvh,
             __half* __restrict__ woh) {
    int b = blockIdx.x;
    const float* in;
    __half* out;
    if (b < N_X / 4096)                          { in = x;  out = xh;  }
    else if ((b -= N_X / 4096)  < N_WQ / 4096)   { in = wq; out = wqh; }
    else if ((b -= N_WQ / 4096) < N_WK / 4096)   { in = wk; out = wkh; }
    else if ((b -= N_WK / 4096) < N_WV / 4096)   { in = wv; out = wvh; }
    else    { b -= N_WV / 4096;                    in = wo; out = woh; }

    const int base = b * 4096 + threadIdx.x * 4;
    float4 v0 = *(const float4*)(in + base);
    float4 v1 = *(const float4*)(in + base + 1024);
    float4 v2 = *(const float4*)(in + base + 2048);
    float4 v3 = *(const float4*)(in + base + 3072);
    *(uint2*)(out + base)        = make_uint2(pack_h2(v0.x, v0.y), pack_h2(v0.z, v0.w));
    *(uint2*)(out + base + 1024) = make_uint2(pack_h2(v1.x, v1.y), pack_h2(v1.z, v1.w));
    *(uint2*)(out + base + 2048) = make_uint2(pack_h2(v2.x, v2.y), pack_h2(v2.z, v2.w));
    *(uint2*)(out + base + 3072) = make_uint2(pack_h2(v3.x, v3.y), pack_h2(v3.z, v3.w));
}
#define CVT_GRID ((N_X + N_WQ + N_WK + N_WV + N_WO) / 4096)

// ---------------- fp16 GEMM: 8-stage ring, TWO BK=32 stages per barrier ----------------
// CTA tile 128(M) x 256(N), 8 warps (2x4), warp tile 64x64. K % 64 == 0 required.
#define HA_STR 40
#define HB_STR 264
#define HA_ST  (128 * HA_STR * 2)               // 10240 B
#define HB_ST  (32 * HB_STR * 2)                // 16896 B
#define HG_SMEM (8 * (HA_ST + HB_ST))           // 217088 B

template <typename OT>
__device__ __forceinline__
void hgemm_rm(const __half* __restrict__ A, const __half* __restrict__ W,
              OT* __restrict__ C, int Ncols, int K, int bm, int bn) {
    extern __shared__ __align__(16) __half hsm[];
    const uint32_t asb = smem_u32(hsm);
    const uint32_t bsb = asb + 8 * HA_ST;

    const int tid  = threadIdx.x;
    const int warp = tid >> 5;
    const int lane = tid & 31;
    const int g    = lane >> 2;
    const int t4   = lane & 3;
    const int wm   = warp >> 2;
    const int wn   = warp & 3;

    const __half* Asrc[2];
    uint32_t Adst[2];
    #pragma unroll
    for (int j = 0; j < 2; j++) {
        int ch = tid + j * 256;
        int row = ch >> 2, kc = (ch & 3) * 8;
        Asrc[j] = A + (size_t)(bm + row) * K + kc;
        Adst[j] = asb + (row * HA_STR + kc) * 2;
    }
    const __half* Bsrc[4];
    uint32_t Bdst[4];
    #pragma unroll
    for (int j = 0; j < 4; j++) {
        int ch = tid + j * 256;
        int row = ch >> 5, c8 = ch & 31;
        Bsrc[j] = W + (size_t)row * Ncols + bn + c8 * 8;
        Bdst[j] = bsb + (row * HB_STR + c8 * 8) * 2;
    }

    const uint32_t aBase = asb + ((wm * 64 + (lane & 7) + ((lane >> 3) & 1) * 8) * HA_STR
                                  + (lane >> 4) * 8) * 2;
    const uint32_t bBase = bsb + (((lane & 7) + ((lane >> 3) & 1) * 8) * HB_STR
                                  + wn * 64 + (lane >> 4) * 8) * 2;

    float acc[4][8][4];
    #pragma unroll
    for (int mi = 0; mi < 4; mi++)
        #pragma unroll
        for (int ni = 0; ni < 8; ni++)
            #pragma unroll
            for (int r = 0; r < 4; r++) acc[mi][ni][r] = 0.0f;

    const size_t bAdv = (size_t)32 * Ncols;
    const int P = K >> 6;                        // stage pairs

    // prologue: stages 0..3, one commit group each
    #pragma unroll
    for (int s = 0; s < 4; s++) {
        const uint32_t ao = s * HA_ST, bo = s * HB_ST;
        const int ko = s << 5;
        #pragma unroll
        for (int j = 0; j < 2; j++) CP_A16(Adst[j] + ao, Asrc[j] + ko);
        #pragma unroll
        for (int j = 0; j < 4; j++) CP_A16(Bdst[j] + bo, Bsrc[j] + (size_t)s * bAdv);
        CP_COMMIT();
    }

    for (int p = 0; p < P; p++) {
        const int s0 = 2 * p;
        if (s0 + 4 < 2 * P) {
            #pragma unroll
            for (int sp = 0; sp < 2; sp++) {
                const int s = s0 + 4 + sp;
                const uint32_t ao = (s & 7) * HA_ST, bo = (s & 7) * HB_ST;
                const int ko = s << 5;
                #pragma unroll
                for (int j = 0; j < 2; j++) CP_A16(Adst[j] + ao, Asrc[j] + ko);
                #pragma unroll
                for (int j = 0; j < 4; j++) CP_A16(Bdst[j] + bo, Bsrc[j] + (size_t)s * bAdv);
                CP_COMMIT();
            }
            CP_WAIT(4);
        } else if (p + 2 == P) {
            CP_WAIT(2);
        } else {
            CP_WAIT(0);
        }
        __syncthreads();   // one barrier per TWO stages

        #pragma unroll
        for (int sp = 0; sp < 2; sp++) {
            const uint32_t ao = ((s0 + sp) & 7) * HA_ST;
            const uint32_t bo = ((s0 + sp) & 7) * HB_ST;
            #pragma unroll
            for (int kb = 0; kb < 2; kb++) {
                uint32_t af[4][4];
                #pragma unroll
                for (int mi = 0; mi < 4; mi++)
                    ldsm_x4(af[mi], aBase + ao + mi * (16 * HA_STR * 2) + kb * 32);
                uint32_t bf[4][4];
                #pragma unroll
                for (int nj = 0; nj < 4; nj++)
                    ldsm_x4_t(bf[nj], bBase + bo + kb * (16 * HB_STR * 2) + nj * 32);
                #pragma unroll
                for (int mi = 0; mi < 4; mi++)
                    #pragma unroll
                    for (int nj = 0; nj < 4; nj++) {
                        mma16816(acc[mi][2 * nj],     af[mi], bf[nj][0], bf[nj][1]);
                        mma16816(acc[mi][2 * nj + 1], af[mi], bf[nj][2], bf[nj][3]);
                    }
            }
        }
    }

    #pragma unroll
    for (int mi = 0; mi < 4; mi++) {
        #pragma unroll
        for (int ni = 0; ni < 8; ni++) {
            int r1 = bm + wm * 64 + mi * 16 + g;
            int c  = bn + wn * 64 + ni * 8 + t4 * 2;
            if (sizeof(OT) == 2) {
                __half* Ch = (__half*)C;
                *(uint32_t*)(Ch + (size_t)r1 * Ncols + c)       = pack_h2(acc[mi][ni][0], acc[mi][ni][1]);
                *(uint32_t*)(Ch + (size_t)(r1 + 8) * Ncols + c) = pack_h2(acc[mi][ni][2], acc[mi][ni][3]);
            } else {
                float* Cf = (float*)C;
                *(float2*)(Cf + (size_t)r1 * Ncols + c)       = make_float2(acc[mi][ni][0], acc[mi][ni][1]);
                *(float2*)(Cf + (size_t)(r1 + 8) * Ncols + c) = make_float2(acc[mi][ni][2], acc[mi][ni][3]);
            }
        }
    }
}

__global__ __launch_bounds__(256, 1)
void hgemm_qkv(const __half* __restrict__ A,
               const __half* __restrict__ Wq, const __half* __restrict__ Wk,
               const __half* __restrict__ Wv,
               __half* __restrict__ Cq, __half* __restrict__ Ck, __half* __restrict__ Cv) {
    const int bx = blockIdx.x;
    const int bm = blockIdx.y * 128;
    if (bx < 16)      hgemm_rm<__half>(A, Wq, Cq, NQH * HD, HID, bm, bx * 256);
    else if (bx < 20) hgemm_rm<__half>(A, Wk, Ck, NKV * HD, HID, bm, (bx - 16) * 256);
    else              hgemm_rm<__half>(A, Wv, Cv, NKV * HD, HID, bm, (bx - 20) * 256);
}

__global__ __launch_bounds__(256, 1)
void hgemm_o(const __half* __restrict__ A, const __half* __restrict__ W,
             float* __restrict__ C) {
    hgemm_rm<float>(A, W, C, HID, NQH * HD, blockIdx.y * 128, blockIdx.x * 256);
}

// ---------------- RMSNorm + RoPE (q and k in ONE launch), in-place fp16 ----------------
#define QROWS (SEQ * NQH)
#define KROWS (SEQ * NKV)

__global__ __launch_bounds__(256)
void rmsnorm_rope_qk(__half* __restrict__ qbuf, __half* __restrict__ kbuf,
                     const float* __restrict__ qw, const float* __restrict__ kw,
                     const float* __restrict__ cosT, const float* __restrict__ sinT,
                     const int* __restrict__ pos_ids, float qscale) {
    const int lane = threadIdx.x & 31;
    int row = blockIdx.x * 8 + (threadIdx.x >> 5);

    __half* buf;
    const float* w;
    float oscale;
    int s;
    if (row < QROWS) {
        buf = qbuf; w = qw; oscale = qscale; s = row / NQH;
    } else {
        row -= QROWS;
        buf = kbuf; w = kw; oscale = 1.0f; s = row / NKV;
    }
    const int c0 = lane * 4;

    __half* rp = buf + (size_t)row * HD;
    uint2 raw = *(const uint2*)(rp + c0);
    __half2 h01 = *(__half2*)&raw.x;
    __half2 h23 = *(__half2*)&raw.y;
    float4 v = make_float4(__low2float(h01), __high2float(h01),
                           __low2float(h23), __high2float(h23));
    float4 wv = *(const float4*)(w + c0);

    float ss = v.x * v.x + v.y * v.y + v.z * v.z + v.w * v.w;
    #pragma unroll
    for (int off = 16; off > 0; off >>= 1)
        ss += __shfl_xor_sync(0xffffffffu, ss, off);
    const float inv = rsqrtf(ss * (1.0f / HD) + 1e-6f);

    float4 xn;
    xn.x = v.x * inv * wv.x; xn.y = v.y * inv * wv.y;
    xn.z = v.z * inv * wv.z; xn.w = v.w * inv * wv.w;

    float px = __shfl_xor_sync(0xffffffffu, xn.x, 16);
    float py = __shfl_xor_sync(0xffffffffu, xn.y, 16);
    float pz = __shfl_xor_sync(0xffffffffu, xn.z, 16);
    float pw = __shfl_xor_sync(0xffffffffu, xn.w, 16);
    const float sgn = (lane < 16) ? -1.0f : 1.0f;

    const int p = pos_ids[s];
    float4 c  = *(const float4*)(cosT + (size_t)p * HD + c0);
    float4 sn = *(const float4*)(sinT + (size_t)p * HD + c0);

    float ox = (xn.x * c.x + sgn * px * sn.x) * oscale;
    float oy = (xn.y * c.y + sgn * py * sn.y) * oscale;
    float oz = (xn.z * c.z + sgn * pz * sn.z) * oscale;
    float ow = (xn.w * c.w + sgn * pw * sn.w) * oscale;

    *(uint2*)(rp + c0) = make_uint2(pack_h2(ox, oy), pack_h2(oz, ow));
}

// ---------------- fp16 flash attention (round-13 config: 4-stage ring, Q hoist) ----------------
#define FSTR 136
#define FQ_HALVES (128 * FSTR)
#define FK_HALVES (64 * FSTR)
#define ATTN_SMEM ((FQ_HALVES + 8 * FK_HALVES) * 2)

__global__ __launch_bounds__(256, 1)
void flash_h(const __half* __restrict__ Qh, const __half* __restrict__ Kh,
             const __half* __restrict__ Vh, __half* __restrict__ Oh) {
    extern __shared__ __align__(16) __half fsm[];
    __half* Qs = fsm;
    __half* Ks = fsm + FQ_HALVES;
    __half* Vs = Ks + 4 * FK_HALVES;

    const int tid  = threadIdx.x;
    const int warp = tid >> 5;
    const int lane = tid & 31;
    const int g    = lane >> 2;
    const int t4   = lane & 3;
    const int wrow = warp * 16;

    const int qb    = gridDim.x - 1 - blockIdx.x;
    const int kvh   = blockIdx.y;
    const int h0    = kvh * 4;
    const int qbase = qb * 32;

    const uint32_t qsb = smem_u32(Qs);
    const uint32_t ksb = smem_u32(Ks);
    const uint32_t vsb = smem_u32(Vs);
    const uint32_t KSTB = FK_HALVES * 2;

    const int nkb = (qbase >> 6) + 1;

    {
        #pragma unroll
        for (int j = 0; j < 8; j++) {
            int c = tid + j * 256;
            int row = c >> 4, c8 = c & 15;
            CP_A16(qsb + (row * FSTR + c8 * 8) * 2,
                   Qh + (size_t)(qbase + (row & 31)) * (NQH * HD)
                      + (h0 + (row >> 5)) * HD + c8 * 8);
        }
        #pragma unroll
        for (int j = 0; j < 4; j++) {
            int c = tid + j * 256;
            int row = c >> 4, c8 = c & 15;
            size_t gi = (size_t)row * (NKV * HD) + kvh * HD + c8 * 8;
            CP_A16(ksb + (row * FSTR + c8 * 8) * 2, Kh + gi);
            CP_A16(vsb + (row * FSTR + c8 * 8) * 2, Vh + gi);
        }
        CP_COMMIT();
        if (nkb > 1) {
            #pragma unroll
            for (int j = 0; j < 4; j++) {
                int c = tid + j * 256;
                int row = c >> 4, c8 = c & 15;
                size_t gi = (size_t)(64 + row) * (NKV * HD) + kvh * HD + c8 * 8;
                CP_A16(ksb + KSTB + (row * FSTR + c8 * 8) * 2, Kh + gi);
                CP_A16(vsb + KSTB + (row * FSTR + c8 * 8) * 2, Vh + gi);
            }
            CP_COMMIT();
        }
    }

    float o[16][4];
    #pragma unroll
    for (int ni = 0; ni < 16; ni++)
        #pragma unroll
        for (int r = 0; r < 4; r++) o[ni][r] = 0.0f;
    float m1 = -INFINITY, m2 = -INFINITY, l1 = 0.0f, l2 = 0.0f;

    const uint32_t qBase = qsb + ((wrow + (lane & 7) + ((lane >> 3) & 1) * 8) * FSTR
                                   + (lane >> 4) * 8) * 2;
    const uint32_t kBase = ksb + (((lane & 7) + (lane >> 4) * 8) * FSTR
                                   + ((lane >> 3) & 1) * 8) * 2;
    const uint32_t vBase = vsb + (((lane & 7) + ((lane >> 3) & 1) * 8) * FSTR
                                   + (lane >> 4) * 8) * 2;

    uint32_t aq[8][4];
    const int seqrel = wrow & 31;

    for (int kb = 0; kb < nkb; kb++) {
        if (kb + 2 < nkb) {
            const int st = (kb + 2) & 3;
            const int kbase2 = (kb + 2) * 64;
            #pragma unroll
            for (int j = 0; j < 4; j++) {
                int c = tid + j * 256;
                int row = c >> 4, c8 = c & 15;
                size_t gi = (size_t)(kbase2 + row) * (NKV * HD) + kvh * HD + c8 * 8;
                CP_A16(ksb + st * KSTB + (row * FSTR + c8 * 8) * 2, Kh + gi);
                CP_A16(vsb + st * KSTB + (row * FSTR + c8 * 8) * 2, Vh + gi);
            }
            CP_COMMIT();
            CP_WAIT(2);
        } else if (kb + 1 < nkb) {
            CP_WAIT(1);
        } else {
            CP_WAIT(0);
        }
        __syncthreads();

        if (kb == 0) {
            #pragma unroll
            for (int k8 = 0; k8 < 8; k8++)
                ldsm_x4(aq[k8], qBase + k8 * 32);
        }

        const uint32_t so = (kb & 3) * KSTB;
        const int kbase = kb * 64;

        float s[8][4];
        #pragma unroll
        for (int ni = 0; ni < 8; ni++)
            #pragma unroll
            for (int r = 0; r < 4; r++) s[ni][r] = 0.0f;

        #pragma unroll
        for (int k8 = 0; k8 < 8; k8++) {
            #pragma unroll
            for (int nj = 0; nj < 4; nj++) {
                uint32_t bk[4];
                ldsm_x4(bk, kBase + so + nj * (16 * FSTR * 2) + k8 * 32);
                mma16816(s[2 * nj],     aq[k8], bk[0], bk[1]);
                mma16816(s[2 * nj + 1], aq[k8], bk[2], bk[3]);
            }
        }

        if (kbase + 63 > qbase + seqrel) {
            const int r1 = qbase + seqrel + g;
            const int r2 = r1 + 8;
            #pragma unroll
            for (int ni = 0; ni < 8; ni++) {
                int c0 = kbase + ni * 8 + t4 * 2;
                if (c0     > r1) s[ni][0] = -1e30f;
                if (c0 + 1 > r1) s[ni][1] = -1e30f;
                if (c0     > r2) s[ni][2] = -1e30f;
                if (c0 + 1 > r2) s[ni][3] = -1e30f;
            }
        }

        float mx1 = -INFINITY, mx2 = -INFINITY;
        #pragma unroll
        for (int ni = 0; ni < 8; ni++) {
            mx1 = fmaxf(mx1, fmaxf(s[ni][0], s[ni][1]));
            mx2 = fmaxf(mx2, fmaxf(s[ni][2], s[ni][3]));
        }
        mx1 = fmaxf(mx1, __shfl_xor_sync(0xffffffffu, mx1, 1));
        mx1 = fmaxf(mx1, __shfl_xor_sync(0xffffffffu, mx1, 2));
        mx2 = fmaxf(mx2, __shfl_xor_sync(0xffffffffu, mx2, 1));
        mx2 = fmaxf(mx2, __shfl_xor_sync(0xffffffffu, mx2, 2));

        float mn1 = fmaxf(m1, mx1), mn2 = fmaxf(m2, mx2);
        float sc1 = exp2f(m1 - mn1), sc2 = exp2f(m2 - mn2);
        m1 = mn1; m2 = mn2;

        float ps1 = 0.0f, ps2 = 0.0f;
        #pragma unroll
        for (int ni = 0; ni < 8; ni++) {
            s[ni][0] = exp2f(s[ni][0] - mn1);
            s[ni][1] = exp2f(s[ni][1] - mn1);
            s[ni][2] = exp2f(s[ni][2] - mn2);
            s[ni][3] = exp2f(s[ni][3] - mn2);
            ps1 += s[ni][0] + s[ni][1];
            ps2 += s[ni][2] + s[ni][3];
        }
        ps1 += __shfl_xor_sync(0xffffffffu, ps1, 1);
        ps1 += __shfl_xor_sync(0xffffffffu, ps1, 2);
        ps2 += __shfl_xor_sync(0xffffffffu, ps2, 1);
        ps2 += __shfl_xor_sync(0xffffffffu, ps2, 2);
        l1 = l1 * sc1 + ps1;
        l2 = l2 * sc2 + ps2;

        #pragma unroll
        for (int ni = 0; ni < 16; ni++) {
            o[ni][0] *= sc1; o[ni][1] *= sc1;
            o[ni][2] *= sc2; o[ni][3] *= sc2;
        }

        #pragma unroll
        for (int j = 0; j < 4; j++) {
            uint32_t ap[4];
            ap[0] = pack_h2(s[2 * j][0],     s[2 * j][1]);
            ap[1] = pack_h2(s[2 * j][2],     s[2 * j][3]);
            ap[2] = pack_h2(s[2 * j + 1][0], s[2 * j + 1][1]);
            ap[3] = pack_h2(s[2 * j + 1][2], s[2 * j + 1][3]);
            #pragma unroll
            for (int nj = 0; nj < 8; nj++) {
                uint32_t bv[4];
                ldsm_x4_t(bv, vBase + so + j * (16 * FSTR * 2) + nj * 32);
                mma16816(o[2 * nj],     ap, bv[0], bv[1]);
                mma16816(o[2 * nj + 1], ap, bv[2], bv[3]);
            }
        }
    }

    const float inv1 = 1.0f / l1;
    const float inv2 = 1.0f / l2;
    const int hOut = h0 + (warp >> 1);
    const int r1 = qbase + seqrel + g;
    #pragma unroll
    for (int ni = 0; ni < 16; ni++) {
        int c = ni * 8 + t4 * 2;
        *(uint32_t*)(Oh + (size_t)r1 * (NQH * HD) + hOut * HD + c) =
            pack_h2(o[ni][0] * inv1, o[ni][1] * inv1);
        *(uint32_t*)(Oh + (size_t)(r1 + 8) * (NQH * HD) + hOut * HD + c) =
            pack_h2(o[ni][2] * inv2, o[ni][3] * inv2);
    }
}

// ---------------- launch ----------------
extern "C" void kernel_launch(void* const* d_in, const int* in_sizes, int n_in,
                              void* d_out, int out_size) {
    const float* x    = (const float*)d_in[0];
    const int*   pos  = (const int*)  d_in[1];
    const float* cosT = (const float*)d_in[2];
    const float* sinT = (const float*)d_in[3];
    // d_in[4] = attn_mask — replicated exactly by causal skip
    const float* Wq   = (const float*)d_in[5];
    const float* Wk   = (const float*)d_in[6];
    const float* Wv   = (const float*)d_in[7];
    const float* Wo   = (const float*)d_in[8];
    const float* qw   = (const float*)d_in[9];
    const float* kw   = (const float*)d_in[10];
    float* out = (float*)d_out;

    __half *xh, *qh, *kh, *vh, *oh, *wqh, *wkh, *wvh, *woh;
    cudaGetSymbolAddress((void**)&xh, g_xh);
    cudaGetSymbolAddress((void**)&qh, g_qh);
    cudaGetSymbolAddress((void**)&kh, g_kh);
    cudaGetSymbolAddress((void**)&vh, g_vh);
    cudaGetSymbolAddress((void**)&oh, g_oh);
    cudaGetSymbolAddress((void**)&wqh, g_Wqh);
    cudaGetSymbolAddress((void**)&wkh, g_Wkh);
    cudaGetSymbolAddress((void**)&wvh, g_Wvh);
    cudaGetSymbolAddress((void**)&woh, g_Woh);

    cudaFuncSetAttribute(flash_h,   cudaFuncAttributeMaxDynamicSharedMemorySize, ATTN_SMEM);
    cudaFuncSetAttribute(hgemm_qkv, cudaFuncAttributeMaxDynamicSharedMemorySize, HG_SMEM);
    cudaFuncSetAttribute(hgemm_o,   cudaFuncAttributeMaxDynamicSharedMemorySize, HG_SMEM);

    // pre-pass: single fused fp32 -> fp16 conversion launch
    cvt_all<<<CVT_GRID, 256>>>(x, Wq, Wk, Wv, Wo, xh, wqh, wkh, wvh, woh);

    // fused QKV projection (8-stage ring, 2 stages per barrier)
    hgemm_qkv<<<dim3(24, SEQ / 128), 256, HG_SMEM>>>(xh, wqh, wkh, wvh, qh, kh, vh);

    // RMSNorm + RoPE in-place on fp16 (q pre-scaled for exp2 softmax)
    rmsnorm_rope_qk<<<(QROWS + KROWS) / 8, 256>>>(qh, kh, qw, kw, cosT, sinT, pos,
                                                  0.08838834764831845f * 1.4426950408889634f);

    // causal flash attention (round-13 config)
    flash_h<<<dim3(SEQ / 32, NKV), 256, ATTN_SMEM>>>(qh, kh, vh, oh);

    // output projection
    hgemm_o<<<dim3(HID / 256, SEQ / 128), 256, HG_SMEM>>>(oh, woh, out);
}